// round 14
// baseline (speedup 1.0000x reference)
#include <cuda_runtime.h>
#include <cuda_bf16.h>
#include <cuda_fp16.h>
#include <cstdint>

#define D 128
#define NMAX 100000
#define EMAX 1600000
#define SCAN_B 1024

// -------- scratch (static device allocations; no cudaMalloc allowed) --------
__device__ __half g_xwh[(size_t)NMAX * D]; // (x@W)*dinv[row], fp16 (25.6 MB)
__device__ float g_dinv[NMAX];
__device__ int   g_deg[NMAX];
__device__ int   g_row[NMAX];
__device__ int   g_cur[NMAX];
__device__ int   g_csr[EMAX];
__device__ int   g_bsum[(NMAX + SCAN_B - 1) / SCAN_B];
__device__ int   g_is64;

// ---------------------------------------------------------------------------
__global__ void detect_init_kernel(const int* ei32, int n) {
    int i = blockIdx.x * blockDim.x + threadIdx.x;
    if (i < n) g_deg[i] = 1;   // self loop
    if (blockIdx.x == 0) {
        __shared__ int s_nonzero;
        if (threadIdx.x == 0) s_nonzero = 0;
        __syncthreads();
        int bad = 0;
        for (int k = threadIdx.x; k < 512; k += blockDim.x)
            if (ei32[2 * k + 1] != 0) bad = 1;
        if (bad) atomicOr(&s_nonzero, 1);
        __syncthreads();
        if (threadIdx.x == 0) g_is64 = s_nonzero ? 0 : 1;
    }
}

__global__ void deg_count(const void* ei, int E) {
    int e = blockIdx.x * blockDim.x + threadIdx.x;
    if (e >= E) return;
    int d;
    if (g_is64) d = (int)((const long long*)ei)[(size_t)E + e];
    else        d = ((const int*)ei)[(size_t)E + e];
    atomicAdd(&g_deg[d], 1);
}

__global__ __launch_bounds__(SCAN_B) void scan1_kernel(int n) {
    __shared__ int sh[SCAN_B];
    int tid = threadIdx.x;
    int i = blockIdx.x * SCAN_B + tid;
    int dg = (i < n) ? g_deg[i] : 1;
    if (i < n) g_dinv[i] = rsqrtf((float)dg);
    int v = (i < n) ? (dg - 1) : 0;
    sh[tid] = v;
    __syncthreads();
    #pragma unroll
    for (int off = 1; off < SCAN_B; off <<= 1) {
        int t = (tid >= off) ? sh[tid - off] : 0;
        __syncthreads();
        sh[tid] += t;
        __syncthreads();
    }
    if (i < n) g_row[i] = sh[tid] - v;
    if (tid == SCAN_B - 1) g_bsum[blockIdx.x] = sh[tid];
}

__global__ __launch_bounds__(SCAN_B) void scan2_kernel(int nb) {
    __shared__ int sh[SCAN_B];
    int tid = threadIdx.x;
    int v = (tid < nb) ? g_bsum[tid] : 0;
    sh[tid] = v;
    __syncthreads();
    #pragma unroll
    for (int off = 1; off < SCAN_B; off <<= 1) {
        int t = (tid >= off) ? sh[tid - off] : 0;
        __syncthreads();
        sh[tid] += t;
        __syncthreads();
    }
    if (tid < nb) g_bsum[tid] = sh[tid] - v;
}

__global__ __launch_bounds__(SCAN_B) void scan3_kernel(int n) {
    int i = blockIdx.x * SCAN_B + threadIdx.x;
    if (i < n) {
        int r = g_row[i] + g_bsum[blockIdx.x];
        g_row[i] = r;
        g_cur[i] = r;
    }
}

__global__ __launch_bounds__(256) void fill_kernel(const void* ei, int E) {
    int e = blockIdx.x * blockDim.x + threadIdx.x;
    if (e >= E) return;
    int s, d;
    if (g_is64) {
        const long long* p = (const long long*)ei;
        s = (int)p[e];
        d = (int)p[(size_t)E + e];
    } else {
        const int* p = (const int*)ei;
        s = p[e];
        d = p[(size_t)E + e];
    }
    int pos = atomicAdd(&g_cur[d], 1);
    g_csr[pos] = s;
}

// ===========================================================================
// GEMM (mma.sync m16n8k16 bf16, fp32 accum, hi/lo split).
// grid.y = sel: 0 -> (x@W)*dinv -> g_xwh (fp16); 1 -> x@Wl -> out (fp32).
// 512 threads = 16 warps, warp tile 32(M)x32(N): low reg pressure -> occ 25%.
// ===========================================================================

#define SSTR 136
#define TILE_B (128 * SSTR * 2)
#define OFF_AHI 0
#define OFF_ALO (TILE_B)
#define OFF_BHI (2 * TILE_B)
#define OFF_BLO (3 * TILE_B)
#define GEMM_SMEM (4 * TILE_B)

__device__ __forceinline__ uint32_t smem_u32(const void* p) {
    uint32_t a;
    asm("{ .reg .u64 t; cvta.to.shared.u64 t, %1; cvt.u32.u64 %0, t; }"
        : "=r"(a) : "l"(p));
    return a;
}

__device__ __forceinline__ void ldsm_x4(uint32_t& r0, uint32_t& r1,
                                        uint32_t& r2, uint32_t& r3, uint32_t addr) {
    asm volatile("ldmatrix.sync.aligned.m8n8.x4.shared.b16 {%0,%1,%2,%3}, [%4];"
                 : "=r"(r0), "=r"(r1), "=r"(r2), "=r"(r3) : "r"(addr));
}

__device__ __forceinline__ void ldsm_x4_t(uint32_t& r0, uint32_t& r1,
                                          uint32_t& r2, uint32_t& r3, uint32_t addr) {
    asm volatile("ldmatrix.sync.aligned.m8n8.x4.trans.shared.b16 {%0,%1,%2,%3}, [%4];"
                 : "=r"(r0), "=r"(r1), "=r"(r2), "=r"(r3) : "r"(addr));
}

__device__ __forceinline__ void mma16816(float* c, const uint32_t* a,
                                         const uint32_t* b) {
    asm volatile(
        "mma.sync.aligned.m16n8k16.row.col.f32.bf16.bf16.f32 "
        "{%0,%1,%2,%3}, {%4,%5,%6,%7}, {%8,%9}, {%0,%1,%2,%3};"
        : "+f"(c[0]), "+f"(c[1]), "+f"(c[2]), "+f"(c[3])
        : "r"(a[0]), "r"(a[1]), "r"(a[2]), "r"(a[3]), "r"(b[0]), "r"(b[1]));
}

__global__ __launch_bounds__(512, 1) void gemm_mma_kernel(
    const float* __restrict__ x,
    const float* __restrict__ W,
    const float* __restrict__ Wl,
    float* __restrict__ outh, int M)
{
    extern __shared__ char smem[];
    const uint32_t sb = smem_u32(smem);
    const int tid  = threadIdx.x;
    const int wid  = tid >> 5;
    const int lane = tid & 31;
    const int row0 = blockIdx.x * 128;
    const int sel  = blockIdx.y;
    const float* B = sel ? Wl : W;

    // ---- A tile: convert x rows to hi/lo bf16, [m][k]; thread = 1/4 row ----
    {
        const int r = tid >> 2;
        const int q = tid & 3;
        const int grow = row0 + r;
        const bool ok = grow < M;
        const float* xr = x + (size_t)(ok ? grow : 0) * D + q * 32;
        char* pHi = smem + OFF_AHI;
        char* pLo = smem + OFF_ALO;
        const uint32_t rb = (uint32_t)(r * SSTR + q * 32) * 2;
        #pragma unroll
        for (int c4 = 0; c4 < 8; c4++) {
            float4 v = ok ? *(const float4*)&xr[c4 * 4]
                          : make_float4(0.f, 0.f, 0.f, 0.f);
            float f[4] = { v.x, v.y, v.z, v.w };
            __nv_bfloat16 h[4], l[4];
            #pragma unroll
            for (int j = 0; j < 4; j++) {
                h[j] = __float2bfloat16(f[j]);
                l[j] = __float2bfloat16(f[j] - __bfloat162float(h[j]));
            }
            *(uint2*)(pHi + rb + c4 * 8) = *(const uint2*)h;
            *(uint2*)(pLo + rb + c4 * 8) = *(const uint2*)l;
        }
    }

    // ---- B tile: natural [k][n], coalesced reads; thread = 1/4 row ----
    {
        const int k = tid >> 2;
        const int q = tid & 3;
        const float* rp = B + (size_t)k * D + q * 32;
        char* pHi = smem + OFF_BHI;
        char* pLo = smem + OFF_BLO;
        const uint32_t rb = (uint32_t)(k * SSTR + q * 32) * 2;
        #pragma unroll
        for (int c4 = 0; c4 < 8; c4++) {
            float4 v = *(const float4*)&rp[c4 * 4];
            float f[4] = { v.x, v.y, v.z, v.w };
            __nv_bfloat16 h[4], l[4];
            #pragma unroll
            for (int j = 0; j < 4; j++) {
                h[j] = __float2bfloat16(f[j]);
                l[j] = __float2bfloat16(f[j] - __bfloat162float(h[j]));
            }
            *(uint2*)(pHi + rb + c4 * 8) = *(const uint2*)h;
            *(uint2*)(pLo + rb + c4 * 8) = *(const uint2*)l;
        }
    }
    __syncthreads();

    // ---- 16 warps: 4 along M (32 rows each) x 4 along N (32 cols each) ----
    const int mi = wid & 3;
    const int ni = wid >> 2;

    float c[2][4][4];
    #pragma unroll
    for (int mt = 0; mt < 2; mt++)
        #pragma unroll
        for (int nt = 0; nt < 4; nt++)
            #pragma unroll
            for (int q = 0; q < 4; q++) c[mt][nt][q] = 0.f;

    const int lmat = lane >> 3;
    const int lr   = lane & 7;
    const int a_rowc = ((lmat & 1) << 3) + lr;
    const int a_colc = (lmat >> 1) << 3;
    const int b_krow = ((lmat >> 1) << 3) + lr;
    const int b_noff = (lmat & 1) << 3;

    #pragma unroll
    for (int p = 0; p < 3; p++) {
        const uint32_t abase = sb + ((p < 2) ? OFF_AHI : OFF_ALO);
        const uint32_t bbase = sb + ((p == 1) ? OFF_BLO : OFF_BHI);
        const uint32_t a_rc = (uint32_t)((mi * 32 + a_rowc) * SSTR + a_colc) * 2;
        const uint32_t b_rc = (uint32_t)(b_krow * SSTR + ni * 32 + b_noff) * 2;

        #pragma unroll
        for (int k0 = 0; k0 < 8; k0++) {
            uint32_t afr[2][4];
            #pragma unroll
            for (int mt = 0; mt < 2; mt++)
                ldsm_x4(afr[mt][0], afr[mt][1], afr[mt][2], afr[mt][3],
                        abase + a_rc + (uint32_t)(k0 * 16) * 2
                              + (uint32_t)(mt * 16 * SSTR) * 2);
            uint32_t bfr[4][2];
            #pragma unroll
            for (int nb = 0; nb < 2; nb++) {
                uint32_t r0, r1, r2, r3;
                ldsm_x4_t(r0, r1, r2, r3,
                          bbase + b_rc + (uint32_t)(k0 * 16 * SSTR) * 2
                                + (uint32_t)(nb * 16) * 2);
                bfr[nb * 2][0]     = r0;  bfr[nb * 2][1]     = r2;
                bfr[nb * 2 + 1][0] = r1;  bfr[nb * 2 + 1][1] = r3;
            }
            #pragma unroll
            for (int mt = 0; mt < 2; mt++)
                #pragma unroll
                for (int nt = 0; nt < 4; nt++)
                    mma16816(c[mt][nt], afr[mt], bfr[nt]);
        }
    }

    // ---- epilogue ----
    const int g   = lane >> 2;
    const int tig = lane & 3;
    if (sel == 0) {
        #pragma unroll
        for (int mt = 0; mt < 2; mt++) {
            const int row = row0 + mi * 32 + mt * 16 + g;
            float di0 = (row < M)     ? g_dinv[row]     : 0.f;
            float di1 = (row + 8 < M) ? g_dinv[row + 8] : 0.f;
            #pragma unroll
            for (int nt = 0; nt < 4; nt++) {
                const int col = ni * 32 + nt * 8 + tig * 2;
                if (row < M)
                    *(__half2*)&g_xwh[(size_t)row * D + col] =
                        __floats2half2_rn(c[mt][nt][0] * di0, c[mt][nt][1] * di0);
                if (row + 8 < M)
                    *(__half2*)&g_xwh[(size_t)(row + 8) * D + col] =
                        __floats2half2_rn(c[mt][nt][2] * di1, c[mt][nt][3] * di1);
            }
        }
    } else {
        #pragma unroll
        for (int mt = 0; mt < 2; mt++) {
            #pragma unroll
            for (int nt = 0; nt < 4; nt++) {
                const int col = ni * 32 + nt * 8 + tig * 2;
                const int row = row0 + mi * 32 + mt * 16 + g;
                if (row < M)
                    *(float2*)&outh[(size_t)row * D + col] =
                        make_float2(c[mt][nt][0], c[mt][nt][1]);
                if (row + 8 < M)
                    *(float2*)&outh[(size_t)(row + 8) * D + col] =
                        make_float2(c[mt][nt][2], c[mt][nt][3]);
            }
        }
    }
}

// ---------------------------------------------------------------------------
// Fused gather + self-loop + residual + LayerNorm. One warp per dst node.
// ---------------------------------------------------------------------------
__global__ __launch_bounds__(256) void gather_ln_kernel(
    float* __restrict__ out,
    const float* __restrict__ b,  const float* __restrict__ bl,
    const float* __restrict__ gamma, const float* __restrict__ beta, int n)
{
    int gtid = blockIdx.x * blockDim.x + threadIdx.x;
    int r    = gtid >> 5;
    int lane = gtid & 31;
    if (r >= n) return;

    const int start = g_row[r];
    const int cnt   = g_deg[r] - 1;
    const float di  = g_dinv[r];
    const int j = lane * 4;

    float ax = 0.f, ay = 0.f, az = 0.f, aw = 0.f;
    for (int base = 0; base < cnt; base += 32) {
        int m = cnt - base;
        int lim = m < 32 ? m : 32;
        int idx = 0;
        if (lane < lim) idx = __ldg(&g_csr[start + base + lane]);
        int k = 0;
        for (; k + 4 <= lim; k += 4) {
            uint2 u[4];
            #pragma unroll
            for (int q = 0; q < 4; q++) {
                int s = __shfl_sync(0xFFFFFFFFu, idx, k + q);
                u[q] = *(const uint2*)&g_xwh[(size_t)s * D + j];
            }
            #pragma unroll
            for (int q = 0; q < 4; q++) {
                float2 pa = __half22float2(*(__half2*)&u[q].x);
                float2 pb = __half22float2(*(__half2*)&u[q].y);
                ax += pa.x; ay += pa.y; az += pb.x; aw += pb.y;
            }
        }
        for (; k < lim; k++) {
            int s = __shfl_sync(0xFFFFFFFFu, idx, k);
            uint2 u = *(const uint2*)&g_xwh[(size_t)s * D + j];
            float2 pa = __half22float2(*(__half2*)&u.x);
            float2 pb = __half22float2(*(__half2*)&u.y);
            ax += pa.x; ay += pa.y; az += pb.x; aw += pb.y;
        }
    }

    // self loop (stored value already carries dinv[r])
    {
        uint2 u = *(const uint2*)&g_xwh[(size_t)r * D + j];
        float2 pa = __half22float2(*(__half2*)&u.x);
        float2 pb = __half22float2(*(__half2*)&u.y);
        ax += pa.x; ay += pa.y; az += pb.x; aw += pb.y;
    }

    float4 res = *(float4*)&out[(size_t)r * D + j];
    float4 b4  = *(const float4*)&b[j];
    float4 l4  = *(const float4*)&bl[j];
    float hx = ax * di + res.x + b4.x + l4.x;
    float hy = ay * di + res.y + b4.y + l4.y;
    float hz = az * di + res.z + b4.z + l4.z;
    float hw = aw * di + res.w + b4.w + l4.w;

    float s = hx + hy + hz + hw;
    #pragma unroll
    for (int o = 16; o > 0; o >>= 1) s += __shfl_xor_sync(0xFFFFFFFFu, s, o);
    float mu = s * (1.f / 128.f);

    float dx = hx - mu, dy = hy - mu, dz = hz - mu, dw = hw - mu;
    float sq = dx * dx + dy * dy + dz * dz + dw * dw;
    #pragma unroll
    for (int o = 16; o > 0; o >>= 1) sq += __shfl_xor_sync(0xFFFFFFFFu, sq, o);
    float rstd = rsqrtf(sq * (1.f / 128.f) + 1e-5f);

    float4 g4 = *(const float4*)&gamma[j];
    float4 e4 = *(const float4*)&beta[j];
    float4 o4;
    o4.x = dx * rstd * g4.x + e4.x;
    o4.y = dy * rstd * g4.y + e4.y;
    o4.z = dz * rstd * g4.z + e4.z;
    o4.w = dw * rstd * g4.w + e4.w;
    *(float4*)&out[(size_t)r * D + j] = o4;
}

// ---------------------------------------------------------------------------
static int s_init = 0;

extern "C" void kernel_launch(void* const* d_in, const int* in_sizes, int n_in,
                              void* d_out, int out_size)
{
    const float* x     = (const float*)d_in[0];
    const void*  ei    = d_in[1];
    const float* W     = (const float*)d_in[2];
    const float* b     = (const float*)d_in[3];
    const float* Wl    = (const float*)d_in[4];
    const float* bl    = (const float*)d_in[5];
    const float* gamma = (const float*)d_in[6];
    const float* beta  = (const float*)d_in[7];
    float* out = (float*)d_out;

    int N = in_sizes[0] / D;
    int E = in_sizes[1] / 2;
    int nb = (N + SCAN_B - 1) / SCAN_B;

    if (!s_init) {
        cudaFuncSetAttribute(gemm_mma_kernel,
                             cudaFuncAttributeMaxDynamicSharedMemorySize, GEMM_SMEM);
        s_init = 1;
    }

    // GEMM kept as 4th launch (ncu profiles launch #4)
    detect_init_kernel<<<(N + 255) / 256, 256>>>((const int*)ei, N);
    deg_count<<<(E + 255) / 256, 256>>>(ei, E);
    scan1_kernel<<<nb, SCAN_B>>>(N);
    dim3 ggrid((N + 127) / 128, 2);
    gemm_mma_kernel<<<ggrid, 512, GEMM_SMEM>>>(x, W, Wl, out, N);
    scan2_kernel<<<1, SCAN_B>>>(nb);
    scan3_kernel<<<nb, SCAN_B>>>(N);
    fill_kernel<<<(E + 255) / 256, 256>>>(ei, E);

    long long lw = (long long)N * 32;
    gather_ln_kernel<<<(unsigned)((lw + 255) / 256), 256>>>(out, b, bl, gamma, beta, N);
}

// round 16
// speedup vs baseline: 1.0769x; 1.0769x over previous
#include <cuda_runtime.h>
#include <cuda_bf16.h>
#include <cuda_fp16.h>
#include <cstdint>

#define D 128
#define NMAX 100000
#define EMAX 1600000
#define SCAN_B 1024

// -------- scratch (static device allocations; no cudaMalloc allowed) --------
__device__ __half g_xwh[(size_t)NMAX * D]; // (x@W)*dinv[row], fp16 (25.6 MB)
__device__ float g_dinv[NMAX];
__device__ int   g_deg[NMAX];
__device__ int   g_row[NMAX];
__device__ int   g_cur[NMAX];
__device__ int   g_csr[EMAX];
__device__ int   g_bsum[(NMAX + SCAN_B - 1) / SCAN_B];
__device__ int   g_is64;

// ---------------------------------------------------------------------------
__global__ void detect_init_kernel(const int* ei32, int n) {
    int i = blockIdx.x * blockDim.x + threadIdx.x;
    if (i < n) g_deg[i] = 1;   // self loop
    if (blockIdx.x == 0) {
        __shared__ int s_nonzero;
        if (threadIdx.x == 0) s_nonzero = 0;
        __syncthreads();
        int bad = 0;
        for (int k = threadIdx.x; k < 512; k += blockDim.x)
            if (ei32[2 * k + 1] != 0) bad = 1;
        if (bad) atomicOr(&s_nonzero, 1);
        __syncthreads();
        if (threadIdx.x == 0) g_is64 = s_nonzero ? 0 : 1;
    }
}

__global__ void deg_count(const void* ei, int E) {
    int e = blockIdx.x * blockDim.x + threadIdx.x;
    if (e >= E) return;
    int d;
    if (g_is64) d = (int)((const long long*)ei)[(size_t)E + e];
    else        d = ((const int*)ei)[(size_t)E + e];
    atomicAdd(&g_deg[d], 1);
}

__global__ __launch_bounds__(SCAN_B) void scan1_kernel(int n) {
    __shared__ int sh[SCAN_B];
    int tid = threadIdx.x;
    int i = blockIdx.x * SCAN_B + tid;
    int dg = (i < n) ? g_deg[i] : 1;
    if (i < n) g_dinv[i] = rsqrtf((float)dg);
    int v = (i < n) ? (dg - 1) : 0;
    sh[tid] = v;
    __syncthreads();
    #pragma unroll
    for (int off = 1; off < SCAN_B; off <<= 1) {
        int t = (tid >= off) ? sh[tid - off] : 0;
        __syncthreads();
        sh[tid] += t;
        __syncthreads();
    }
    if (i < n) g_row[i] = sh[tid] - v;
    if (tid == SCAN_B - 1) g_bsum[blockIdx.x] = sh[tid];
}

__global__ __launch_bounds__(SCAN_B) void scan2_kernel(int nb) {
    __shared__ int sh[SCAN_B];
    int tid = threadIdx.x;
    int v = (tid < nb) ? g_bsum[tid] : 0;
    sh[tid] = v;
    __syncthreads();
    #pragma unroll
    for (int off = 1; off < SCAN_B; off <<= 1) {
        int t = (tid >= off) ? sh[tid - off] : 0;
        __syncthreads();
        sh[tid] += t;
        __syncthreads();
    }
    if (tid < nb) g_bsum[tid] = sh[tid] - v;
}

__global__ __launch_bounds__(SCAN_B) void scan3_kernel(int n) {
    int i = blockIdx.x * SCAN_B + threadIdx.x;
    if (i < n) {
        int r = g_row[i] + g_bsum[blockIdx.x];
        g_row[i] = r;
        g_cur[i] = r;
    }
}

__global__ __launch_bounds__(256) void fill_kernel(const void* ei, int E) {
    int e = blockIdx.x * blockDim.x + threadIdx.x;
    if (e >= E) return;
    int s, d;
    if (g_is64) {
        const long long* p = (const long long*)ei;
        s = (int)p[e];
        d = (int)p[(size_t)E + e];
    } else {
        const int* p = (const int*)ei;
        s = p[e];
        d = p[(size_t)E + e];
    }
    int pos = atomicAdd(&g_cur[d], 1);
    g_csr[pos] = s;
}

// ===========================================================================
// GEMM (mma.sync m16n8k16 bf16, fp32 accum, hi/lo split — FUSED passes).
// Per k-step: load afr_hi/afr_lo/bfr_hi/bfr_lo ONCE (8 ldsm), issue all
// 3 products (hi*hi + hi*lo + lo*hi) into one accumulator: 24 MMAs.
// grid.y = sel: 0 -> (x@W)*dinv -> g_xwh (fp16); 1 -> x@Wl -> out (fp32).
// ===========================================================================

#define SSTR 136
#define TILE_B (128 * SSTR * 2)
#define OFF_AHI 0
#define OFF_ALO (TILE_B)
#define OFF_BHI (2 * TILE_B)
#define OFF_BLO (3 * TILE_B)
#define GEMM_SMEM (4 * TILE_B)

__device__ __forceinline__ uint32_t smem_u32(const void* p) {
    uint32_t a;
    asm("{ .reg .u64 t; cvta.to.shared.u64 t, %1; cvt.u32.u64 %0, t; }"
        : "=r"(a) : "l"(p));
    return a;
}

__device__ __forceinline__ void ldsm_x4(uint32_t& r0, uint32_t& r1,
                                        uint32_t& r2, uint32_t& r3, uint32_t addr) {
    asm volatile("ldmatrix.sync.aligned.m8n8.x4.shared.b16 {%0,%1,%2,%3}, [%4];"
                 : "=r"(r0), "=r"(r1), "=r"(r2), "=r"(r3) : "r"(addr));
}

__device__ __forceinline__ void ldsm_x4_t(uint32_t& r0, uint32_t& r1,
                                          uint32_t& r2, uint32_t& r3, uint32_t addr) {
    asm volatile("ldmatrix.sync.aligned.m8n8.x4.trans.shared.b16 {%0,%1,%2,%3}, [%4];"
                 : "=r"(r0), "=r"(r1), "=r"(r2), "=r"(r3) : "r"(addr));
}

__device__ __forceinline__ void mma16816(float* c, const uint32_t* a,
                                         const uint32_t* b) {
    asm volatile(
        "mma.sync.aligned.m16n8k16.row.col.f32.bf16.bf16.f32 "
        "{%0,%1,%2,%3}, {%4,%5,%6,%7}, {%8,%9}, {%0,%1,%2,%3};"
        : "+f"(c[0]), "+f"(c[1]), "+f"(c[2]), "+f"(c[3])
        : "r"(a[0]), "r"(a[1]), "r"(a[2]), "r"(a[3]), "r"(b[0]), "r"(b[1]));
}

__global__ __launch_bounds__(512, 1) void gemm_mma_kernel(
    const float* __restrict__ x,
    const float* __restrict__ W,
    const float* __restrict__ Wl,
    float* __restrict__ outh, int M)
{
    extern __shared__ char smem[];
    const uint32_t sb = smem_u32(smem);
    const int tid  = threadIdx.x;
    const int wid  = tid >> 5;
    const int lane = tid & 31;
    const int row0 = blockIdx.x * 128;
    const int sel  = blockIdx.y;
    const float* B = sel ? Wl : W;

    // ---- A tile: convert x rows to hi/lo bf16, [m][k]; thread = 1/4 row ----
    {
        const int r = tid >> 2;
        const int q = tid & 3;
        const int grow = row0 + r;
        const bool ok = grow < M;
        const float* xr = x + (size_t)(ok ? grow : 0) * D + q * 32;
        char* pHi = smem + OFF_AHI;
        char* pLo = smem + OFF_ALO;
        const uint32_t rb = (uint32_t)(r * SSTR + q * 32) * 2;
        #pragma unroll
        for (int c4 = 0; c4 < 8; c4++) {
            float4 v = ok ? *(const float4*)&xr[c4 * 4]
                          : make_float4(0.f, 0.f, 0.f, 0.f);
            float f[4] = { v.x, v.y, v.z, v.w };
            __nv_bfloat16 h[4], l[4];
            #pragma unroll
            for (int j = 0; j < 4; j++) {
                h[j] = __float2bfloat16(f[j]);
                l[j] = __float2bfloat16(f[j] - __bfloat162float(h[j]));
            }
            *(uint2*)(pHi + rb + c4 * 8) = *(const uint2*)h;
            *(uint2*)(pLo + rb + c4 * 8) = *(const uint2*)l;
        }
    }

    // ---- B tile: natural [k][n], coalesced reads; thread = 1/4 row ----
    {
        const int k = tid >> 2;
        const int q = tid & 3;
        const float* rp = B + (size_t)k * D + q * 32;
        char* pHi = smem + OFF_BHI;
        char* pLo = smem + OFF_BLO;
        const uint32_t rb = (uint32_t)(k * SSTR + q * 32) * 2;
        #pragma unroll
        for (int c4 = 0; c4 < 8; c4++) {
            float4 v = *(const float4*)&rp[c4 * 4];
            float f[4] = { v.x, v.y, v.z, v.w };
            __nv_bfloat16 h[4], l[4];
            #pragma unroll
            for (int j = 0; j < 4; j++) {
                h[j] = __float2bfloat16(f[j]);
                l[j] = __float2bfloat16(f[j] - __bfloat162float(h[j]));
            }
            *(uint2*)(pHi + rb + c4 * 8) = *(const uint2*)h;
            *(uint2*)(pLo + rb + c4 * 8) = *(const uint2*)l;
        }
    }
    __syncthreads();

    // ---- 16 warps: 4 along M (32 rows) x 4 along N (32 cols) ----
    const int mi = wid & 3;
    const int ni = wid >> 2;

    float c[2][4][4];
    #pragma unroll
    for (int mt = 0; mt < 2; mt++)
        #pragma unroll
        for (int nt = 0; nt < 4; nt++)
            #pragma unroll
            for (int q = 0; q < 4; q++) c[mt][nt][q] = 0.f;

    const int lmat = lane >> 3;
    const int lr   = lane & 7;
    const int a_rowc = ((lmat & 1) << 3) + lr;
    const int a_colc = (lmat >> 1) << 3;
    const int b_krow = ((lmat >> 1) << 3) + lr;
    const int b_noff = (lmat & 1) << 3;

    const uint32_t a_rc = (uint32_t)((mi * 32 + a_rowc) * SSTR + a_colc) * 2;
    const uint32_t b_rc = (uint32_t)(b_krow * SSTR + ni * 32 + b_noff) * 2;

    #pragma unroll
    for (int k0 = 0; k0 < 8; k0++) {
        const uint32_t ak = a_rc + (uint32_t)(k0 * 16) * 2;
        const uint32_t bk = b_rc + (uint32_t)(k0 * 16 * SSTR) * 2;

        uint32_t ah[2][4], al[2][4];
        #pragma unroll
        for (int mt = 0; mt < 2; mt++) {
            ldsm_x4(ah[mt][0], ah[mt][1], ah[mt][2], ah[mt][3],
                    sb + OFF_AHI + ak + (uint32_t)(mt * 16 * SSTR) * 2);
            ldsm_x4(al[mt][0], al[mt][1], al[mt][2], al[mt][3],
                    sb + OFF_ALO + ak + (uint32_t)(mt * 16 * SSTR) * 2);
        }
        uint32_t bh[4][2], bl_[4][2];
        #pragma unroll
        for (int nb = 0; nb < 2; nb++) {
            uint32_t r0, r1, r2, r3;
            ldsm_x4_t(r0, r1, r2, r3,
                      sb + OFF_BHI + bk + (uint32_t)(nb * 16) * 2);
            bh[nb * 2][0]     = r0;  bh[nb * 2][1]     = r2;
            bh[nb * 2 + 1][0] = r1;  bh[nb * 2 + 1][1] = r3;
            ldsm_x4_t(r0, r1, r2, r3,
                      sb + OFF_BLO + bk + (uint32_t)(nb * 16) * 2);
            bl_[nb * 2][0]     = r0;  bl_[nb * 2][1]     = r2;
            bl_[nb * 2 + 1][0] = r1;  bl_[nb * 2 + 1][1] = r3;
        }

        #pragma unroll
        for (int mt = 0; mt < 2; mt++)
            #pragma unroll
            for (int nt = 0; nt < 4; nt++) {
                mma16816(c[mt][nt], ah[mt], bh[nt]);   // hi*hi
                mma16816(c[mt][nt], ah[mt], bl_[nt]);  // hi*lo
                mma16816(c[mt][nt], al[mt], bh[nt]);   // lo*hi
            }
    }

    // ---- epilogue ----
    const int g   = lane >> 2;
    const int tig = lane & 3;
    if (sel == 0) {
        #pragma unroll
        for (int mt = 0; mt < 2; mt++) {
            const int row = row0 + mi * 32 + mt * 16 + g;
            float di0 = (row < M)     ? g_dinv[row]     : 0.f;
            float di1 = (row + 8 < M) ? g_dinv[row + 8] : 0.f;
            #pragma unroll
            for (int nt = 0; nt < 4; nt++) {
                const int col = ni * 32 + nt * 8 + tig * 2;
                if (row < M)
                    *(__half2*)&g_xwh[(size_t)row * D + col] =
                        __floats2half2_rn(c[mt][nt][0] * di0, c[mt][nt][1] * di0);
                if (row + 8 < M)
                    *(__half2*)&g_xwh[(size_t)(row + 8) * D + col] =
                        __floats2half2_rn(c[mt][nt][2] * di1, c[mt][nt][3] * di1);
            }
        }
    } else {
        #pragma unroll
        for (int mt = 0; mt < 2; mt++) {
            #pragma unroll
            for (int nt = 0; nt < 4; nt++) {
                const int col = ni * 32 + nt * 8 + tig * 2;
                const int row = row0 + mi * 32 + mt * 16 + g;
                if (row < M)
                    *(float2*)&outh[(size_t)row * D + col] =
                        make_float2(c[mt][nt][0], c[mt][nt][1]);
                if (row + 8 < M)
                    *(float2*)&outh[(size_t)(row + 8) * D + col] =
                        make_float2(c[mt][nt][2], c[mt][nt][3]);
            }
        }
    }
}

// ---------------------------------------------------------------------------
// Fused gather + self-loop + residual + LayerNorm. One warp per dst node.
// ---------------------------------------------------------------------------
__global__ __launch_bounds__(256) void gather_ln_kernel(
    float* __restrict__ out,
    const float* __restrict__ b,  const float* __restrict__ bl,
    const float* __restrict__ gamma, const float* __restrict__ beta, int n)
{
    int gtid = blockIdx.x * blockDim.x + threadIdx.x;
    int r    = gtid >> 5;
    int lane = gtid & 31;
    if (r >= n) return;

    const int start = g_row[r];
    const int cnt   = g_deg[r] - 1;
    const float di  = g_dinv[r];
    const int j = lane * 4;

    float ax = 0.f, ay = 0.f, az = 0.f, aw = 0.f;
    for (int base = 0; base < cnt; base += 32) {
        int m = cnt - base;
        int lim = m < 32 ? m : 32;
        int idx = 0;
        if (lane < lim) idx = __ldg(&g_csr[start + base + lane]);
        int k = 0;
        for (; k + 4 <= lim; k += 4) {
            uint2 u[4];
            #pragma unroll
            for (int q = 0; q < 4; q++) {
                int s = __shfl_sync(0xFFFFFFFFu, idx, k + q);
                u[q] = *(const uint2*)&g_xwh[(size_t)s * D + j];
            }
            #pragma unroll
            for (int q = 0; q < 4; q++) {
                float2 pa = __half22float2(*(__half2*)&u[q].x);
                float2 pb = __half22float2(*(__half2*)&u[q].y);
                ax += pa.x; ay += pa.y; az += pb.x; aw += pb.y;
            }
        }
        for (; k < lim; k++) {
            int s = __shfl_sync(0xFFFFFFFFu, idx, k);
            uint2 u = *(const uint2*)&g_xwh[(size_t)s * D + j];
            float2 pa = __half22float2(*(__half2*)&u.x);
            float2 pb = __half22float2(*(__half2*)&u.y);
            ax += pa.x; ay += pa.y; az += pb.x; aw += pb.y;
        }
    }

    // self loop (stored value already carries dinv[r])
    {
        uint2 u = *(const uint2*)&g_xwh[(size_t)r * D + j];
        float2 pa = __half22float2(*(__half2*)&u.x);
        float2 pb = __half22float2(*(__half2*)&u.y);
        ax += pa.x; ay += pa.y; az += pb.x; aw += pb.y;
    }

    float4 res = *(float4*)&out[(size_t)r * D + j];
    float4 b4  = *(const float4*)&b[j];
    float4 l4  = *(const float4*)&bl[j];
    float hx = ax * di + res.x + b4.x + l4.x;
    float hy = ay * di + res.y + b4.y + l4.y;
    float hz = az * di + res.z + b4.z + l4.z;
    float hw = aw * di + res.w + b4.w + l4.w;

    float s = hx + hy + hz + hw;
    #pragma unroll
    for (int o = 16; o > 0; o >>= 1) s += __shfl_xor_sync(0xFFFFFFFFu, s, o);
    float mu = s * (1.f / 128.f);

    float dx = hx - mu, dy = hy - mu, dz = hz - mu, dw = hw - mu;
    float sq = dx * dx + dy * dy + dz * dz + dw * dw;
    #pragma unroll
    for (int o = 16; o > 0; o >>= 1) sq += __shfl_xor_sync(0xFFFFFFFFu, sq, o);
    float rstd = rsqrtf(sq * (1.f / 128.f) + 1e-5f);

    float4 g4 = *(const float4*)&gamma[j];
    float4 e4 = *(const float4*)&beta[j];
    float4 o4;
    o4.x = dx * rstd * g4.x + e4.x;
    o4.y = dy * rstd * g4.y + e4.y;
    o4.z = dz * rstd * g4.z + e4.z;
    o4.w = dw * rstd * g4.w + e4.w;
    *(float4*)&out[(size_t)r * D + j] = o4;
}

// ---------------------------------------------------------------------------
static int s_init = 0;

extern "C" void kernel_launch(void* const* d_in, const int* in_sizes, int n_in,
                              void* d_out, int out_size)
{
    const float* x     = (const float*)d_in[0];
    const void*  ei    = d_in[1];
    const float* W     = (const float*)d_in[2];
    const float* b     = (const float*)d_in[3];
    const float* Wl    = (const float*)d_in[4];
    const float* bl    = (const float*)d_in[5];
    const float* gamma = (const float*)d_in[6];
    const float* beta  = (const float*)d_in[7];
    float* out = (float*)d_out;

    int N = in_sizes[0] / D;
    int E = in_sizes[1] / 2;
    int nb = (N + SCAN_B - 1) / SCAN_B;

    if (!s_init) {
        cudaFuncSetAttribute(gemm_mma_kernel,
                             cudaFuncAttributeMaxDynamicSharedMemorySize, GEMM_SMEM);
        s_init = 1;
    }

    // GEMM kept as 4th launch (ncu profiles launch #4)
    detect_init_kernel<<<(N + 255) / 256, 256>>>((const int*)ei, N);
    deg_count<<<(E + 255) / 256, 256>>>(ei, E);
    scan1_kernel<<<nb, SCAN_B>>>(N);
    dim3 ggrid((N + 127) / 128, 2);
    gemm_mma_kernel<<<ggrid, 512, GEMM_SMEM>>>(x, W, Wl, out, N);
    scan2_kernel<<<1, SCAN_B>>>(nb);
    scan3_kernel<<<nb, SCAN_B>>>(N);
    fill_kernel<<<(E + 255) / 256, 256>>>(ei, E);

    long long lw = (long long)N * 32;
    gather_ln_kernel<<<(unsigned)((lw + 255) / 256), 256>>>(out, b, bl, gamma, beta, N);
}

// round 17
// speedup vs baseline: 1.0863x; 1.0088x over previous
#include <cuda_runtime.h>
#include <cuda_bf16.h>
#include <cuda_fp16.h>
#include <cstdint>

#define D 128
#define NMAX 100000
#define EMAX 1600000
#define SCAN_B 1024

// -------- scratch (static device allocations; no cudaMalloc allowed) --------
__device__ __half g_xwh[(size_t)NMAX * D]; // (x@W)*dinv[row], fp16 (25.6 MB)
__device__ float g_dinv[NMAX];
__device__ int   g_deg[NMAX];
__device__ int   g_row[NMAX];
__device__ int   g_cur[NMAX];
__device__ int   g_csr[EMAX];
__device__ int   g_bsum[(NMAX + SCAN_B - 1) / SCAN_B];
__device__ int   g_is64;

// ---------------------------------------------------------------------------
__global__ void detect_init_kernel(const int* ei32, int n) {
    int i = blockIdx.x * blockDim.x + threadIdx.x;
    if (i < n) g_deg[i] = 1;   // self loop
    if (blockIdx.x == 0) {
        __shared__ int s_nonzero;
        if (threadIdx.x == 0) s_nonzero = 0;
        __syncthreads();
        int bad = 0;
        for (int k = threadIdx.x; k < 512; k += blockDim.x)
            if (ei32[2 * k + 1] != 0) bad = 1;
        if (bad) atomicOr(&s_nonzero, 1);
        __syncthreads();
        if (threadIdx.x == 0) g_is64 = s_nonzero ? 0 : 1;
    }
}

__global__ void deg_count(const void* ei, int E) {
    int e = blockIdx.x * blockDim.x + threadIdx.x;
    if (e >= E) return;
    int d;
    if (g_is64) d = (int)((const long long*)ei)[(size_t)E + e];
    else        d = ((const int*)ei)[(size_t)E + e];
    atomicAdd(&g_deg[d], 1);
}

__global__ __launch_bounds__(SCAN_B) void scan1_kernel(int n) {
    __shared__ int sh[SCAN_B];
    int tid = threadIdx.x;
    int i = blockIdx.x * SCAN_B + tid;
    int dg = (i < n) ? g_deg[i] : 1;
    if (i < n) g_dinv[i] = rsqrtf((float)dg);
    int v = (i < n) ? (dg - 1) : 0;
    sh[tid] = v;
    __syncthreads();
    #pragma unroll
    for (int off = 1; off < SCAN_B; off <<= 1) {
        int t = (tid >= off) ? sh[tid - off] : 0;
        __syncthreads();
        sh[tid] += t;
        __syncthreads();
    }
    if (i < n) g_row[i] = sh[tid] - v;
    if (tid == SCAN_B - 1) g_bsum[blockIdx.x] = sh[tid];
}

__global__ __launch_bounds__(SCAN_B) void scan2_kernel(int nb) {
    __shared__ int sh[SCAN_B];
    int tid = threadIdx.x;
    int v = (tid < nb) ? g_bsum[tid] : 0;
    sh[tid] = v;
    __syncthreads();
    #pragma unroll
    for (int off = 1; off < SCAN_B; off <<= 1) {
        int t = (tid >= off) ? sh[tid - off] : 0;
        __syncthreads();
        sh[tid] += t;
        __syncthreads();
    }
    if (tid < nb) g_bsum[tid] = sh[tid] - v;
}

__global__ __launch_bounds__(SCAN_B) void scan3_kernel(int n) {
    int i = blockIdx.x * SCAN_B + threadIdx.x;
    if (i < n) {
        int r = g_row[i] + g_bsum[blockIdx.x];
        g_row[i] = r;
        g_cur[i] = r;
    }
}

__global__ __launch_bounds__(256) void fill_kernel(const void* ei, int E) {
    int e = blockIdx.x * blockDim.x + threadIdx.x;
    if (e >= E) return;
    int s, d;
    if (g_is64) {
        const long long* p = (const long long*)ei;
        s = (int)p[e];
        d = (int)p[(size_t)E + e];
    } else {
        const int* p = (const int*)ei;
        s = p[e];
        d = p[(size_t)E + e];
    }
    int pos = atomicAdd(&g_cur[d], 1);
    g_csr[pos] = s;
}

// ===========================================================================
// GEMM (mma.sync m16n8k16 bf16, fp32 accum, hi/lo split — FUSED passes).
// Per k-step: load afr_hi/afr_lo/bfr_hi/bfr_lo ONCE (8 ldsm), issue all
// 3 products (hi*hi + hi*lo + lo*hi) into one accumulator: 24 MMAs.
// grid.y = sel: 0 -> (x@W)*dinv -> g_xwh (fp16); 1 -> x@Wl -> out (fp32).
// ===========================================================================

#define SSTR 136
#define TILE_B (128 * SSTR * 2)
#define OFF_AHI 0
#define OFF_ALO (TILE_B)
#define OFF_BHI (2 * TILE_B)
#define OFF_BLO (3 * TILE_B)
#define GEMM_SMEM (4 * TILE_B)

__device__ __forceinline__ uint32_t smem_u32(const void* p) {
    uint32_t a;
    asm("{ .reg .u64 t; cvta.to.shared.u64 t, %1; cvt.u32.u64 %0, t; }"
        : "=r"(a) : "l"(p));
    return a;
}

__device__ __forceinline__ void ldsm_x4(uint32_t& r0, uint32_t& r1,
                                        uint32_t& r2, uint32_t& r3, uint32_t addr) {
    asm volatile("ldmatrix.sync.aligned.m8n8.x4.shared.b16 {%0,%1,%2,%3}, [%4];"
                 : "=r"(r0), "=r"(r1), "=r"(r2), "=r"(r3) : "r"(addr));
}

__device__ __forceinline__ void ldsm_x4_t(uint32_t& r0, uint32_t& r1,
                                          uint32_t& r2, uint32_t& r3, uint32_t addr) {
    asm volatile("ldmatrix.sync.aligned.m8n8.x4.trans.shared.b16 {%0,%1,%2,%3}, [%4];"
                 : "=r"(r0), "=r"(r1), "=r"(r2), "=r"(r3) : "r"(addr));
}

__device__ __forceinline__ void mma16816(float* c, const uint32_t* a,
                                         const uint32_t* b) {
    asm volatile(
        "mma.sync.aligned.m16n8k16.row.col.f32.bf16.bf16.f32 "
        "{%0,%1,%2,%3}, {%4,%5,%6,%7}, {%8,%9}, {%0,%1,%2,%3};"
        : "+f"(c[0]), "+f"(c[1]), "+f"(c[2]), "+f"(c[3])
        : "r"(a[0]), "r"(a[1]), "r"(a[2]), "r"(a[3]), "r"(b[0]), "r"(b[1]));
}

__global__ __launch_bounds__(512, 1) void gemm_mma_kernel(
    const float* __restrict__ x,
    const float* __restrict__ W,
    const float* __restrict__ Wl,
    float* __restrict__ outh, int M)
{
    extern __shared__ char smem[];
    const uint32_t sb = smem_u32(smem);
    const int tid  = threadIdx.x;
    const int wid  = tid >> 5;
    const int lane = tid & 31;
    const int row0 = blockIdx.x * 128;
    const int sel  = blockIdx.y;
    const float* B = sel ? Wl : W;

    // ---- A tile: convert x rows to hi/lo bf16, [m][k]; thread = 1/4 row ----
    {
        const int r = tid >> 2;
        const int q = tid & 3;
        const int grow = row0 + r;
        const bool ok = grow < M;
        const float* xr = x + (size_t)(ok ? grow : 0) * D + q * 32;
        char* pHi = smem + OFF_AHI;
        char* pLo = smem + OFF_ALO;
        const uint32_t rb = (uint32_t)(r * SSTR + q * 32) * 2;
        #pragma unroll
        for (int c4 = 0; c4 < 8; c4++) {
            float4 v = ok ? *(const float4*)&xr[c4 * 4]
                          : make_float4(0.f, 0.f, 0.f, 0.f);
            float f[4] = { v.x, v.y, v.z, v.w };
            __nv_bfloat16 h[4], l[4];
            #pragma unroll
            for (int j = 0; j < 4; j++) {
                h[j] = __float2bfloat16(f[j]);
                l[j] = __float2bfloat16(f[j] - __bfloat162float(h[j]));
            }
            *(uint2*)(pHi + rb + c4 * 8) = *(const uint2*)h;
            *(uint2*)(pLo + rb + c4 * 8) = *(const uint2*)l;
        }
    }

    // ---- B tile: natural [k][n], coalesced reads; thread = 1/4 row ----
    {
        const int k = tid >> 2;
        const int q = tid & 3;
        const float* rp = B + (size_t)k * D + q * 32;
        char* pHi = smem + OFF_BHI;
        char* pLo = smem + OFF_BLO;
        const uint32_t rb = (uint32_t)(k * SSTR + q * 32) * 2;
        #pragma unroll
        for (int c4 = 0; c4 < 8; c4++) {
            float4 v = *(const float4*)&rp[c4 * 4];
            float f[4] = { v.x, v.y, v.z, v.w };
            __nv_bfloat16 h[4], l[4];
            #pragma unroll
            for (int j = 0; j < 4; j++) {
                h[j] = __float2bfloat16(f[j]);
                l[j] = __float2bfloat16(f[j] - __bfloat162float(h[j]));
            }
            *(uint2*)(pHi + rb + c4 * 8) = *(const uint2*)h;
            *(uint2*)(pLo + rb + c4 * 8) = *(const uint2*)l;
        }
    }
    __syncthreads();

    // ---- 16 warps: 4 along M (32 rows) x 4 along N (32 cols) ----
    const int mi = wid & 3;
    const int ni = wid >> 2;

    float c[2][4][4];
    #pragma unroll
    for (int mt = 0; mt < 2; mt++)
        #pragma unroll
        for (int nt = 0; nt < 4; nt++)
            #pragma unroll
            for (int q = 0; q < 4; q++) c[mt][nt][q] = 0.f;

    const int lmat = lane >> 3;
    const int lr   = lane & 7;
    const int a_rowc = ((lmat & 1) << 3) + lr;
    const int a_colc = (lmat >> 1) << 3;
    const int b_krow = ((lmat >> 1) << 3) + lr;
    const int b_noff = (lmat & 1) << 3;

    const uint32_t a_rc = (uint32_t)((mi * 32 + a_rowc) * SSTR + a_colc) * 2;
    const uint32_t b_rc = (uint32_t)(b_krow * SSTR + ni * 32 + b_noff) * 2;

    #pragma unroll
    for (int k0 = 0; k0 < 8; k0++) {
        const uint32_t ak = a_rc + (uint32_t)(k0 * 16) * 2;
        const uint32_t bk = b_rc + (uint32_t)(k0 * 16 * SSTR) * 2;

        uint32_t ah[2][4], al[2][4];
        #pragma unroll
        for (int mt = 0; mt < 2; mt++) {
            ldsm_x4(ah[mt][0], ah[mt][1], ah[mt][2], ah[mt][3],
                    sb + OFF_AHI + ak + (uint32_t)(mt * 16 * SSTR) * 2);
            ldsm_x4(al[mt][0], al[mt][1], al[mt][2], al[mt][3],
                    sb + OFF_ALO + ak + (uint32_t)(mt * 16 * SSTR) * 2);
        }
        uint32_t bh[4][2], bl_[4][2];
        #pragma unroll
        for (int nb = 0; nb < 2; nb++) {
            uint32_t r0, r1, r2, r3;
            ldsm_x4_t(r0, r1, r2, r3,
                      sb + OFF_BHI + bk + (uint32_t)(nb * 16) * 2);
            bh[nb * 2][0]     = r0;  bh[nb * 2][1]     = r2;
            bh[nb * 2 + 1][0] = r1;  bh[nb * 2 + 1][1] = r3;
            ldsm_x4_t(r0, r1, r2, r3,
                      sb + OFF_BLO + bk + (uint32_t)(nb * 16) * 2);
            bl_[nb * 2][0]     = r0;  bl_[nb * 2][1]     = r2;
            bl_[nb * 2 + 1][0] = r1;  bl_[nb * 2 + 1][1] = r3;
        }

        #pragma unroll
        for (int mt = 0; mt < 2; mt++)
            #pragma unroll
            for (int nt = 0; nt < 4; nt++) {
                mma16816(c[mt][nt], ah[mt], bh[nt]);   // hi*hi
                mma16816(c[mt][nt], ah[mt], bl_[nt]);  // hi*lo
                mma16816(c[mt][nt], al[mt], bh[nt]);   // lo*hi
            }
    }

    // ---- epilogue ----
    const int g   = lane >> 2;
    const int tig = lane & 3;
    if (sel == 0) {
        #pragma unroll
        for (int mt = 0; mt < 2; mt++) {
            const int row = row0 + mi * 32 + mt * 16 + g;
            float di0 = (row < M)     ? g_dinv[row]     : 0.f;
            float di1 = (row + 8 < M) ? g_dinv[row + 8] : 0.f;
            #pragma unroll
            for (int nt = 0; nt < 4; nt++) {
                const int col = ni * 32 + nt * 8 + tig * 2;
                if (row < M)
                    *(__half2*)&g_xwh[(size_t)row * D + col] =
                        __floats2half2_rn(c[mt][nt][0] * di0, c[mt][nt][1] * di0);
                if (row + 8 < M)
                    *(__half2*)&g_xwh[(size_t)(row + 8) * D + col] =
                        __floats2half2_rn(c[mt][nt][2] * di1, c[mt][nt][3] * di1);
            }
        }
    } else {
        #pragma unroll
        for (int mt = 0; mt < 2; mt++) {
            #pragma unroll
            for (int nt = 0; nt < 4; nt++) {
                const int col = ni * 32 + nt * 8 + tig * 2;
                const int row = row0 + mi * 32 + mt * 16 + g;
                if (row < M)
                    *(float2*)&outh[(size_t)row * D + col] =
                        make_float2(c[mt][nt][0], c[mt][nt][1]);
                if (row + 8 < M)
                    *(float2*)&outh[(size_t)(row + 8) * D + col] =
                        make_float2(c[mt][nt][2], c[mt][nt][3]);
            }
        }
    }
}

// ---------------------------------------------------------------------------
// Fused gather + self-loop + residual + LayerNorm. One warp per dst node.
// ---------------------------------------------------------------------------
__global__ __launch_bounds__(256) void gather_ln_kernel(
    float* __restrict__ out,
    const float* __restrict__ b,  const float* __restrict__ bl,
    const float* __restrict__ gamma, const float* __restrict__ beta, int n)
{
    int gtid = blockIdx.x * blockDim.x + threadIdx.x;
    int r    = gtid >> 5;
    int lane = gtid & 31;
    if (r >= n) return;

    const int start = g_row[r];
    const int cnt   = g_deg[r] - 1;
    const float di  = g_dinv[r];
    const int j = lane * 4;

    float ax = 0.f, ay = 0.f, az = 0.f, aw = 0.f;
    for (int base = 0; base < cnt; base += 32) {
        int m = cnt - base;
        int lim = m < 32 ? m : 32;
        int idx = 0;
        if (lane < lim) idx = __ldg(&g_csr[start + base + lane]);
        int k = 0;
        for (; k + 4 <= lim; k += 4) {
            uint2 u[4];
            #pragma unroll
            for (int q = 0; q < 4; q++) {
                int s = __shfl_sync(0xFFFFFFFFu, idx, k + q);
                u[q] = *(const uint2*)&g_xwh[(size_t)s * D + j];
            }
            #pragma unroll
            for (int q = 0; q < 4; q++) {
                float2 pa = __half22float2(*(__half2*)&u[q].x);
                float2 pb = __half22float2(*(__half2*)&u[q].y);
                ax += pa.x; ay += pa.y; az += pb.x; aw += pb.y;
            }
        }
        for (; k < lim; k++) {
            int s = __shfl_sync(0xFFFFFFFFu, idx, k);
            uint2 u = *(const uint2*)&g_xwh[(size_t)s * D + j];
            float2 pa = __half22float2(*(__half2*)&u.x);
            float2 pb = __half22float2(*(__half2*)&u.y);
            ax += pa.x; ay += pa.y; az += pb.x; aw += pb.y;
        }
    }

    // self loop (stored value already carries dinv[r])
    {
        uint2 u = *(const uint2*)&g_xwh[(size_t)r * D + j];
        float2 pa = __half22float2(*(__half2*)&u.x);
        float2 pb = __half22float2(*(__half2*)&u.y);
        ax += pa.x; ay += pa.y; az += pb.x; aw += pb.y;
    }

    float4 res = *(float4*)&out[(size_t)r * D + j];
    float4 b4  = *(const float4*)&b[j];
    float4 l4  = *(const float4*)&bl[j];
    float hx = ax * di + res.x + b4.x + l4.x;
    float hy = ay * di + res.y + b4.y + l4.y;
    float hz = az * di + res.z + b4.z + l4.z;
    float hw = aw * di + res.w + b4.w + l4.w;

    float s = hx + hy + hz + hw;
    #pragma unroll
    for (int o = 16; o > 0; o >>= 1) s += __shfl_xor_sync(0xFFFFFFFFu, s, o);
    float mu = s * (1.f / 128.f);

    float dx = hx - mu, dy = hy - mu, dz = hz - mu, dw = hw - mu;
    float sq = dx * dx + dy * dy + dz * dz + dw * dw;
    #pragma unroll
    for (int o = 16; o > 0; o >>= 1) sq += __shfl_xor_sync(0xFFFFFFFFu, sq, o);
    float rstd = rsqrtf(sq * (1.f / 128.f) + 1e-5f);

    float4 g4 = *(const float4*)&gamma[j];
    float4 e4 = *(const float4*)&beta[j];
    float4 o4;
    o4.x = dx * rstd * g4.x + e4.x;
    o4.y = dy * rstd * g4.y + e4.y;
    o4.z = dz * rstd * g4.z + e4.z;
    o4.w = dw * rstd * g4.w + e4.w;
    *(float4*)&out[(size_t)r * D + j] = o4;
}

// ---------------------------------------------------------------------------
static int s_init = 0;

extern "C" void kernel_launch(void* const* d_in, const int* in_sizes, int n_in,
                              void* d_out, int out_size)
{
    const float* x     = (const float*)d_in[0];
    const void*  ei    = d_in[1];
    const float* W     = (const float*)d_in[2];
    const float* b     = (const float*)d_in[3];
    const float* Wl    = (const float*)d_in[4];
    const float* bl    = (const float*)d_in[5];
    const float* gamma = (const float*)d_in[6];
    const float* beta  = (const float*)d_in[7];
    float* out = (float*)d_out;

    int N = in_sizes[0] / D;
    int E = in_sizes[1] / 2;
    int nb = (N + SCAN_B - 1) / SCAN_B;

    if (!s_init) {
        cudaFuncSetAttribute(gemm_mma_kernel,
                             cudaFuncAttributeMaxDynamicSharedMemorySize, GEMM_SMEM);
        s_init = 1;
    }

    // GEMM kept as 4th launch (ncu profiles launch #4)
    detect_init_kernel<<<(N + 255) / 256, 256>>>((const int*)ei, N);
    deg_count<<<(E + 255) / 256, 256>>>(ei, E);
    scan1_kernel<<<nb, SCAN_B>>>(N);
    dim3 ggrid((N + 127) / 128, 2);
    gemm_mma_kernel<<<ggrid, 512, GEMM_SMEM>>>(x, W, Wl, out, N);
    scan2_kernel<<<1, SCAN_B>>>(nb);
    scan3_kernel<<<nb, SCAN_B>>>(N);
    fill_kernel<<<(E + 255) / 256, 256>>>(ei, E);

    long long lw = (long long)N * 32;
    gather_ln_kernel<<<(unsigned)((lw + 255) / 256), 256>>>(out, b, bl, gamma, beta, N);
}